// round 3
// baseline (speedup 1.0000x reference)
#include <cuda_runtime.h>
#include <cstdint>

#define NB 64
#define NS 512
#define NH 768
#define NL 9

// scratch (static device globals — no allocation)
__device__ float g_feats[NB * NS * NL];
__device__ float g_nll[NB];

// ---------------------------------------------------------------------------
// Phase 1: feats[tok][l] = hidden[tok] . W[l] + b[l]
// 4 tokens per warp; W chunk reused across the 4 tokens (W is 27.6KB -> L1
// resident). Scalar f32 accumulators keep regs ~70 -> 3 CTA/SM -> enough
// warps+MLP to approach the DRAM roofline (100 MB of hidden read once).
// Next-chunk hidden prefetch overlaps LDG latency with the FFMA block.
// ---------------------------------------------------------------------------
__global__ __launch_bounds__(256) void gemm_kernel(
    const float* __restrict__ hidden, const float* __restrict__ W,
    const float* __restrict__ bias)
{
    int gw   = (blockIdx.x * 256 + threadIdx.x) >> 5;   // global warp id, 0..8191
    int lane = threadIdx.x & 31;
    int tok0 = gw * 4;

    const float4* h0 = (const float4*)(hidden + (size_t)(tok0 + 0) * NH);
    const float4* h1 = (const float4*)(hidden + (size_t)(tok0 + 1) * NH);
    const float4* h2 = (const float4*)(hidden + (size_t)(tok0 + 2) * NH);
    const float4* h3 = (const float4*)(hidden + (size_t)(tok0 + 3) * NH);

    float acc[4][NL];
#pragma unroll
    for (int t = 0; t < 4; t++)
#pragma unroll
        for (int l = 0; l < NL; l++) acc[t][l] = 0.0f;

    // prefetch chunk 0 (each chunk = 128 floats = 32 lanes * float4)
    float4 hv[4], hvn[4];
    hv[0] = __ldg(h0 + lane);
    hv[1] = __ldg(h1 + lane);
    hv[2] = __ldg(h2 + lane);
    hv[3] = __ldg(h3 + lane);

#pragma unroll
    for (int c = 0; c < 6; c++) {
        if (c < 5) {                       // prefetch next chunk's hidden
            int off = (c + 1) * 32 + lane;
            hvn[0] = __ldg(h0 + off);
            hvn[1] = __ldg(h1 + off);
            hvn[2] = __ldg(h2 + off);
            hvn[3] = __ldg(h3 + off);
        }
#pragma unroll
        for (int l = 0; l < NL; l++) {
            float4 wv = __ldg((const float4*)(W + l * NH + c * 128) + lane);
#pragma unroll
            for (int t = 0; t < 4; t++) {
                float a = acc[t][l];
                a = fmaf(hv[t].x, wv.x, a);
                a = fmaf(hv[t].y, wv.y, a);
                a = fmaf(hv[t].z, wv.z, a);
                a = fmaf(hv[t].w, wv.w, a);
                acc[t][l] = a;
            }
        }
#pragma unroll
        for (int t = 0; t < 4; t++) hv[t] = hvn[t];
    }

#pragma unroll
    for (int t = 0; t < 4; t++) {
#pragma unroll
        for (int l = 0; l < NL; l++) {
            float v = acc[t][l];
#pragma unroll
            for (int o = 16; o > 0; o >>= 1)
                v += __shfl_xor_sync(0xffffffffu, v, o);
            int oidx = t * NL + l;
            if (lane == (oidx & 31)) {
                g_feats[(size_t)(tok0 + t) * NL + l] = v + __ldg(bias + l);
            }
        }
    }
}

// ---------------------------------------------------------------------------
// dtype-agnostic mask length (mask values are 0/1; layout may be 1-byte bool
// or 4-byte int32/float32). Probe: byte[1] nonzero <=> 1-byte layout
// (element 1 is always true because len >= S/2). Counting nonzero 32-bit
// words covers both int32 and float32.
// ---------------------------------------------------------------------------
__device__ __forceinline__ int mask_len_warp(const unsigned char* mask, int b, int lane) {
    int c = 0;
    if (mask[1] != 0) {
        const uint4* mp = (const uint4*)(mask + (size_t)b * NS);
        uint4 mv = mp[lane];                 // 16 bytes per lane
        c = __dp4a((int)mv.x, 0x01010101, c);
        c = __dp4a((int)mv.y, 0x01010101, c);
        c = __dp4a((int)mv.z, 0x01010101, c);
        c = __dp4a((int)mv.w, 0x01010101, c);
    } else {
        const uint4* mp = (const uint4*)((const uint32_t*)mask + (size_t)b * NS);
#pragma unroll
        for (int k = 0; k < 4; k++) {
            uint4 mv = mp[lane * 4 + k];     // 16 words per lane
            c += (mv.x != 0u) + (mv.y != 0u) + (mv.z != 0u) + (mv.w != 0u);
        }
    }
#pragma unroll
    for (int o = 16; o > 0; o >>= 1) c += __shfl_xor_sync(0xffffffffu, c, o);
    return c;
}

// ---------------------------------------------------------------------------
// Phase 2: per-batch CRF forward scan (warp 0) + gold-path score (warp 1).
// Exp-domain recurrence: q'_j = (sum_i q_i * exp(trans[i][j])) * exp(f_t[j]),
// alpha = C + log q, renormalized every 8 steps. Mask is a prefix -> loop to len.
// ---------------------------------------------------------------------------
__global__ __launch_bounds__(128) void crf_kernel(
    const float* __restrict__ startv, const float* __restrict__ endv,
    const float* __restrict__ trans, const int* __restrict__ labels,
    const unsigned char* __restrict__ mask)
{
    __shared__ float s_ef[NS * NL];          // exp(feats) for this batch row
    __shared__ float s_trans[NL * NL];
    __shared__ float s_score, s_logden;

    int b    = blockIdx.x;
    int tid  = threadIdx.x;
    int lane = tid & 31;
    int wid  = tid >> 5;

    const float* fb = g_feats + (size_t)b * NS * NL;

    // preload exp(feats) into smem (all 128 threads)
    {
        const float4* src = (const float4*)fb;
        float4*       dst = (float4*)s_ef;
        for (int i = tid; i < NS * NL / 4; i += 128) {
            float4 v = __ldg(src + i);
            float4 e;
            e.x = __expf(v.x); e.y = __expf(v.y);
            e.z = __expf(v.z); e.w = __expf(v.w);
            dst[i] = e;
        }
    }
    if (tid < NL * NL) s_trans[tid] = trans[tid];
    __syncthreads();

    int len = mask_len_warp(mask, b, lane);

    if (wid == 0) {
        // ----- forward scan -----
        int jc = lane < NL ? lane : NL - 1;  // lanes 9..31 duplicate lane 8 (harmless)
        float Ecol[NL];
#pragma unroll
        for (int i = 0; i < NL; i++) Ecol[i] = __expf(s_trans[i * NL + jc]);

        float a0 = __ldg(startv + jc) + fb[jc];
        float C  = __shfl_sync(0xffffffffu, a0, 0);
        float qn = __expf(a0 - C);
        float q[NL];
#pragma unroll
        for (int i = 0; i < NL; i++) q[i] = __shfl_sync(0xffffffffu, qn, i);

        float eft = s_ef[NL + jc];           // prefetch t=1 (len >= 256 always)
        for (int t = 1; t < len; t++) {
            int   tn  = (t + 1 < NS) ? t + 1 : NS - 1;
            float efn = s_ef[tn * NL + jc];  // prefetch next step

            float p0 = q[0]*Ecol[0], p1 = q[1]*Ecol[1], p2 = q[2]*Ecol[2];
            float p3 = q[3]*Ecol[3], p4 = q[4]*Ecol[4], p5 = q[5]*Ecol[5];
            float p6 = q[6]*Ecol[6], p7 = q[7]*Ecol[7], p8 = q[8]*Ecol[8];
            float s  = (((p0 + p1) + (p2 + p3)) + ((p4 + p5) + (p6 + p7))) + p8;
            qn = s * eft;
#pragma unroll
            for (int i = 0; i < NL; i++) q[i] = __shfl_sync(0xffffffffu, qn, i);
            eft = efn;

            if ((t & 7) == 0) {              // renormalize every 8 steps
                float r   = q[0];
                C        += __logf(r);
                float inv = __fdividef(1.0f, r);
#pragma unroll
                for (int i = 0; i < NL; i++) q[i] *= inv;
            }
        }

        float term = (lane < NL) ? q[jc] * __expf(__ldg(endv + jc)) : 0.0f;
#pragma unroll
        for (int o = 16; o > 0; o >>= 1)
            term += __shfl_xor_sync(0xffffffffu, term, o);
        if (lane == 0) s_logden = C + __logf(term);
    } else if (wid == 1) {
        // ----- gold-path score -----
        const int* lab = labels + (size_t)b * NS;
        float sc = 0.0f;
        for (int t = lane; t < NS; t += 32) {
            if (t >= 1 && t < len) {
                int lp = __ldg(lab + t - 1);
                int lc = __ldg(lab + t);
                sc += s_trans[lp * NL + lc] + fb[t * NL + lc];
            }
        }
        if (lane == 0) {
            int l0 = __ldg(lab);
            sc += __ldg(startv + l0) + fb[l0];
            sc += __ldg(endv + __ldg(lab + len - 1));
        }
#pragma unroll
        for (int o = 16; o > 0; o >>= 1)
            sc += __shfl_xor_sync(0xffffffffu, sc, o);
        if (lane == 0) s_score = sc;
    }
    __syncthreads();
    if (tid == 0) g_nll[b] = s_logden - s_score;
}

// ---------------------------------------------------------------------------
// Phase 3: mean over batch -> scalar output
// ---------------------------------------------------------------------------
__global__ void reduce_kernel(float* out) {
    int tid = threadIdx.x;                   // 64 threads
    float v = g_nll[tid];
#pragma unroll
    for (int o = 16; o > 0; o >>= 1)
        v += __shfl_xor_sync(0xffffffffu, v, o);
    __shared__ float s[2];
    if ((tid & 31) == 0) s[tid >> 5] = v;
    __syncthreads();
    if (tid == 0) out[0] = (s[0] + s[1]) * (1.0f / NB);
}

extern "C" void kernel_launch(void* const* d_in, const int* in_sizes, int n_in,
                              void* d_out, int out_size) {
    const float*         hidden = (const float*)d_in[0];
    const float*         W      = (const float*)d_in[1];
    const float*         bias   = (const float*)d_in[2];
    const float*         startv = (const float*)d_in[3];
    const float*         endv   = (const float*)d_in[4];
    const float*         trans  = (const float*)d_in[5];
    const int*           labels = (const int*)d_in[6];
    const unsigned char* mask   = (const unsigned char*)d_in[7];

    gemm_kernel<<<1024, 256>>>(hidden, W, bias);
    crf_kernel<<<NB, 128>>>(startv, endv, trans, labels, mask);
    reduce_kernel<<<1, 64>>>((float*)d_out);
}

// round 5
// speedup vs baseline: 1.8714x; 1.8714x over previous
#include <cuda_runtime.h>
#include <cstdint>

#define NB 64
#define NS 512
#define NH 768
#define NL 9
#define NCH 8
#define CHS 64

typedef unsigned long long ull;

// scratch (static device globals — no allocation)
__device__ float g_feats[NB * NS * NL];
__device__ float g_nll[NB];

__device__ __forceinline__ ull ffma2(ull a, ull b, ull c) {
    ull d;
    asm("fma.rn.f32x2 %0, %1, %2, %3;" : "=l"(d) : "l"(a), "l"(b), "l"(c));
    return d;
}

// ---------------------------------------------------------------------------
// Phase 1: feats[tok][l] = hidden[tok] . W[l] + b[l]
// W staged in smem (removes 226 MB of W L1 traffic -> L1 carries only hidden).
// 2 tokens per warp. Packed f32x2 FMA over adjacent k-dims: float4 loads
// reinterpret directly as two f32-pairs -> zero packing cost, FFMA issue /2.
// All 6 hidden chunks prefetched up front -> LDG latency fully overlapped.
// ---------------------------------------------------------------------------
__global__ __launch_bounds__(512, 1) void gemm_kernel(
    const float* __restrict__ hidden, const float* __restrict__ W,
    const float* __restrict__ bias)
{
    __shared__ float s_w[NL * NH];               // 27648 B

    int tid  = threadIdx.x;
    int lane = tid & 31;
    int wid  = tid >> 5;
    int gw   = blockIdx.x * 16 + wid;            // 0..16383
    int tok0 = gw * 2;

    // issue hidden prefetch first (12 LDG.128 per thread, independent)
    const ulonglong2* h0 = (const ulonglong2*)(hidden + (size_t)tok0 * NH);
    const ulonglong2* h1 = (const ulonglong2*)(hidden + (size_t)(tok0 + 1) * NH);
    ulonglong2 hv[6][2];
#pragma unroll
    for (int c = 0; c < 6; c++) {
        hv[c][0] = __ldg(h0 + c * 32 + lane);
        hv[c][1] = __ldg(h1 + c * 32 + lane);
    }

    // cooperative W load into smem (1728 float4)
    for (int i = tid; i < NL * NH / 4; i += 512)
        ((float4*)s_w)[i] = __ldg((const float4*)W + i);
    __syncthreads();

    ull acc[2][NL];
#pragma unroll
    for (int t = 0; t < 2; t++)
#pragma unroll
        for (int l = 0; l < NL; l++) acc[t][l] = 0ull;

#pragma unroll
    for (int c = 0; c < 6; c++) {
#pragma unroll
        for (int l = 0; l < NL; l++) {
            ulonglong2 wv = *(const ulonglong2*)(s_w + l * NH + c * 128 + lane * 4);
            acc[0][l] = ffma2(hv[c][0].x, wv.x, acc[0][l]);
            acc[0][l] = ffma2(hv[c][0].y, wv.y, acc[0][l]);
            acc[1][l] = ffma2(hv[c][1].x, wv.x, acc[1][l]);
            acc[1][l] = ffma2(hv[c][1].y, wv.y, acc[1][l]);
        }
    }

#pragma unroll
    for (int t = 0; t < 2; t++) {
#pragma unroll
        for (int l = 0; l < NL; l++) {
            float lo, hi;
            asm("mov.b64 {%0, %1}, %2;" : "=f"(lo), "=f"(hi) : "l"(acc[t][l]));
            float v = lo + hi;
#pragma unroll
            for (int o = 16; o > 0; o >>= 1)
                v += __shfl_xor_sync(0xffffffffu, v, o);
            int oidx = t * NL + l;                // 0..17 < 32
            if (lane == oidx)
                g_feats[(size_t)(tok0 + t) * NL + l] = v + __ldg(bias + l);
        }
    }
}

// ---------------------------------------------------------------------------
// dtype-agnostic mask length (prefix mask; 1-byte bool or 4-byte int/float).
// ---------------------------------------------------------------------------
__device__ __forceinline__ int mask_len_warp(const unsigned char* mask, int b, int lane) {
    int c = 0;
    if (mask[1] != 0) {
        const uint4* mp = (const uint4*)(mask + (size_t)b * NS);
        uint4 mv = mp[lane];
        c = __dp4a((int)mv.x, 0x01010101, c);
        c = __dp4a((int)mv.y, 0x01010101, c);
        c = __dp4a((int)mv.z, 0x01010101, c);
        c = __dp4a((int)mv.w, 0x01010101, c);
    } else {
        const uint4* mp = (const uint4*)((const uint32_t*)mask + (size_t)b * NS);
#pragma unroll
        for (int k = 0; k < 4; k++) {
            uint4 mv = mp[lane * 4 + k];
            c += (mv.x != 0u) + (mv.y != 0u) + (mv.z != 0u) + (mv.w != 0u);
        }
    }
#pragma unroll
    for (int o = 16; o > 0; o >>= 1) c += __shfl_xor_sync(0xffffffffu, c, o);
    return c;
}

// ---------------------------------------------------------------------------
// Phase 2: chunked CRF forward. Block = one batch row, 25 warps.
// Warps 0..23: chunk c = w/3 (64 steps), rowgroup g = w%3; lanes 0..26 hold
// (basis row r = 3g + lane/9, col j = lane%9) of the chunk transfer matrix in
// exp domain (renorm every 8 steps). Warp 24: gold-path score.
// Warp 0 then folds alpha0 through the 8 log-domain matrices.
// ---------------------------------------------------------------------------
__global__ __launch_bounds__(800) void crf_kernel(
    const float* __restrict__ startv, const float* __restrict__ endv,
    const float* __restrict__ trans, const int* __restrict__ labels,
    const unsigned char* __restrict__ mask)
{
    __shared__ float s_ef[NS * NL];              // exp(feats)  18432 B
    __shared__ float s_logM[NCH][NL][NL];        // log-domain chunk matrices
    __shared__ float s_score, s_logden;

    int b    = blockIdx.x;
    int tid  = threadIdx.x;
    int lane = tid & 31;
    int wid  = tid >> 5;

    const float* fb = g_feats + (size_t)b * NS * NL;

    // preload exp(feats)
    {
        const float4* src = (const float4*)fb;
        float4*       dst = (float4*)s_ef;
        for (int i = tid; i < NS * NL / 4; i += 800) {
            float4 v = __ldg(src + i);
            float4 e;
            e.x = __expf(v.x); e.y = __expf(v.y);
            e.z = __expf(v.z); e.w = __expf(v.w);
            dst[i] = e;
        }
    }
    __syncthreads();

    int len = mask_len_warp(mask, b, lane);

    if (wid < 24) {
        int c  = wid / 3, g = wid % 3;
        int jl = lane < 27 ? lane : 26;          // lanes 27..31 mirror lane 26
        int rl = jl / 9, j = jl % 9;
        int r  = g * 3 + rl;
        int base = rl * 9;

        float Ecol[NL];
#pragma unroll
        for (int i = 0; i < NL; i++) Ecol[i] = __expf(__ldg(trans + i * NL + j));

        float q = (j == r) ? 1.0f : 0.0f;        // basis row r, exp domain
        float C = 0.0f;

        int tstart = (c == 0) ? 1 : c * CHS;
        int tend   = min((c + 1) * CHS, len);    // warp-uniform

        float eft = s_ef[tstart * NL + j];
        for (int t = tstart; t < tend; t++) {
            float efn = s_ef[min(t + 1, NS - 1) * NL + j];
            float q0 = __shfl_sync(0xffffffffu, q, base + 0);
            float q1 = __shfl_sync(0xffffffffu, q, base + 1);
            float q2 = __shfl_sync(0xffffffffu, q, base + 2);
            float q3 = __shfl_sync(0xffffffffu, q, base + 3);
            float q4 = __shfl_sync(0xffffffffu, q, base + 4);
            float q5 = __shfl_sync(0xffffffffu, q, base + 5);
            float q6 = __shfl_sync(0xffffffffu, q, base + 6);
            float q7 = __shfl_sync(0xffffffffu, q, base + 7);
            float q8 = __shfl_sync(0xffffffffu, q, base + 8);
            float p  = ((q0*Ecol[0] + q1*Ecol[1]) + (q2*Ecol[2] + q3*Ecol[3]))
                     + ((q4*Ecol[4] + q5*Ecol[5]) + (q6*Ecol[6] + q7*Ecol[7]))
                     + q8*Ecol[8];
            float qn = p * eft;
            eft = efn;
            if ((t & 7) == 7) {                  // renorm by pre-step row value
                C += __logf(q0);
                qn *= __fdividef(1.0f, q0);
            }
            q = qn;
        }
        if (lane < 27)
            s_logM[c][r][j] = C + __logf(q);     // -inf if chunk fully masked
    } else if (wid == 24) {
        // gold-path score
        const int* lab = labels + (size_t)b * NS;
        float sc = 0.0f;
        for (int t = lane; t < NS; t += 32) {
            if (t >= 1 && t < len) {
                int lp = __ldg(lab + t - 1);
                int lc = __ldg(lab + t);
                sc += __ldg(trans + lp * NL + lc) + fb[t * NL + lc];
            }
        }
        if (lane == 0) {
            int l0 = __ldg(lab);
            sc += __ldg(startv + l0) + fb[l0];
            sc += __ldg(endv + __ldg(lab + len - 1));
        }
#pragma unroll
        for (int o = 16; o > 0; o >>= 1)
            sc += __shfl_xor_sync(0xffffffffu, sc, o);
        if (lane == 0) s_score = sc;
    }
    __syncthreads();

    if (wid == 0) {
        // fold alpha0 through chunk matrices (log domain), lanes 0..8 live
        int j = lane < 9 ? lane : 8;
        float v = __ldg(startv + j) + fb[j];     // log alpha_0
        for (int cc = 0; cc < NCH; cc++) {
            if (cc * CHS < len) {
                float x0 = __shfl_sync(0xffffffffu, v, 0) + s_logM[cc][0][j];
                float x1 = __shfl_sync(0xffffffffu, v, 1) + s_logM[cc][1][j];
                float x2 = __shfl_sync(0xffffffffu, v, 2) + s_logM[cc][2][j];
                float x3 = __shfl_sync(0xffffffffu, v, 3) + s_logM[cc][3][j];
                float x4 = __shfl_sync(0xffffffffu, v, 4) + s_logM[cc][4][j];
                float x5 = __shfl_sync(0xffffffffu, v, 5) + s_logM[cc][5][j];
                float x6 = __shfl_sync(0xffffffffu, v, 6) + s_logM[cc][6][j];
                float x7 = __shfl_sync(0xffffffffu, v, 7) + s_logM[cc][7][j];
                float x8 = __shfl_sync(0xffffffffu, v, 8) + s_logM[cc][8][j];
                float m = fmaxf(fmaxf(fmaxf(fmaxf(x0,x1),fmaxf(x2,x3)),
                                       fmaxf(fmaxf(x4,x5),fmaxf(x6,x7))), x8);
                float s = ((__expf(x0-m)+__expf(x1-m)) + (__expf(x2-m)+__expf(x3-m)))
                        + ((__expf(x4-m)+__expf(x5-m)) + (__expf(x6-m)+__expf(x7-m)))
                        + __expf(x8-m);
                v = m + __logf(s);
            }
        }
        float t = (lane < 9) ? v + __ldg(endv + j) : -3.0e38f;
        float m = t;
#pragma unroll
        for (int o = 16; o > 0; o >>= 1) m = fmaxf(m, __shfl_xor_sync(0xffffffffu, m, o));
        float e = (lane < 9) ? __expf(t - m) : 0.0f;
#pragma unroll
        for (int o = 16; o > 0; o >>= 1) e += __shfl_xor_sync(0xffffffffu, e, o);
        if (lane == 0) s_logden = m + __logf(e);
    }
    __syncthreads();
    if (tid == 0) g_nll[b] = s_logden - s_score;
}

// ---------------------------------------------------------------------------
// Phase 3: mean over batch -> scalar output
// ---------------------------------------------------------------------------
__global__ void reduce_kernel(float* out) {
    int tid = threadIdx.x;                       // 64 threads
    float v = g_nll[tid];
#pragma unroll
    for (int o = 16; o > 0; o >>= 1)
        v += __shfl_xor_sync(0xffffffffu, v, o);
    __shared__ float s[2];
    if ((tid & 31) == 0) s[tid >> 5] = v;
    __syncthreads();
    if (tid == 0) out[0] = (s[0] + s[1]) * (1.0f / NB);
}

extern "C" void kernel_launch(void* const* d_in, const int* in_sizes, int n_in,
                              void* d_out, int out_size) {
    const float*         hidden = (const float*)d_in[0];
    const float*         W      = (const float*)d_in[1];
    const float*         bias   = (const float*)d_in[2];
    const float*         startv = (const float*)d_in[3];
    const float*         endv   = (const float*)d_in[4];
    const float*         trans  = (const float*)d_in[5];
    const int*           labels = (const int*)d_in[6];
    const unsigned char* mask   = (const unsigned char*)d_in[7];

    gemm_kernel<<<1024, 512>>>(hidden, W, bias);
    crf_kernel<<<NB, 800>>>(startv, endv, trans, labels, mask);
    reduce_kernel<<<1, 64>>>((float*)d_out);
}